// round 1
// baseline (speedup 1.0000x reference)
#include <cuda_runtime.h>
#include <cstdint>

#define NSEQ 2048
#define DD 512
#define VV 512

// ---------------- device scratch (no allocations allowed) ----------------
static __device__ float g_X [NSEQ * DD];
static __device__ float g_XW[NSEQ * DD];
static __device__ float g_H [NSEQ * DD];
static __device__ float g_O [NSEQ * VV];
static __device__ int   g_is64;

// ---------------- helpers ----------------
__device__ __forceinline__ uint32_t ctarank() {
    uint32_t r; asm("mov.u32 %0, %%cluster_ctarank;" : "=r"(r)); return r;
}
__device__ __forceinline__ uint32_t s2u(const void* p) {
    uint32_t a;
    asm("{ .reg .u64 t; cvta.to.shared.u64 t, %1; cvt.u32.u64 %0, t; }" : "=r"(a) : "l"(p));
    return a;
}
__device__ __forceinline__ void dsmem_st(uint32_t laddr, uint32_t trank, float v) {
    uint32_t r;
    asm volatile("mapa.shared::cluster.u32 %0, %1, %2;" : "=r"(r) : "r"(laddr), "r"(trank));
    asm volatile("st.shared::cluster.f32 [%0], %1;" :: "r"(r), "f"(v) : "memory");
}
__device__ __forceinline__ void cluster_sync_() {
    asm volatile("barrier.cluster.arrive.aligned;" ::: "memory");
    asm volatile("barrier.cluster.wait.aligned;"   ::: "memory");
}
__device__ __forceinline__ float ex2f_(float x) {
    float y; asm("ex2.approx.f32 %0, %1;" : "=f"(y) : "f"(x)); return y;
}
__device__ __forceinline__ float lg2f_(float x) {
    float y; asm("lg2.approx.f32 %0, %1;" : "=f"(y) : "f"(x)); return y;
}

// ---------------- int64-vs-int32 index detection ----------------
// JAX requests int64 but without x64 the array is int32. If int64: odd 32-bit
// words (high halves) are all zero. We only touch the first 2048 words, which
// exist in both layouts.
__global__ void detect_kernel(const int* __restrict__ w) {
    __shared__ int any;
    if (threadIdx.x == 0) any = 0;
    __syncthreads();
    int acc = 0;
    for (int i = threadIdx.x; i < NSEQ / 2; i += blockDim.x) acc |= w[2 * i + 1];
    if (acc) atomicOr(&any, 1);
    __syncthreads();
    if (threadIdx.x == 0) g_is64 = (any == 0) ? 1 : 0;
}

// ---------------- embedding gather ----------------
__global__ void gather_kernel(const void* __restrict__ nums, const float* __restrict__ emb) {
    int t = blockIdx.x;
    long long idx = g_is64 ? ((const long long*)nums)[t]
                           : (long long)((const int*)nums)[t];
    const float4* src = (const float4*)(emb + (size_t)idx * DD);
    float4* dst = (float4*)(&g_X[(size_t)t * DD]);
    int i = threadIdx.x;              // blockDim = 128 == DD/4
    dst[i] = src[i];
}

// ---------------- SIMT tiled SGEMM: C[2048,512] = A[2048,512]@B[512,512] + bias ----------------
__global__ __launch_bounds__(256)
void gemm_bias(const float* __restrict__ A, const float* __restrict__ B,
               const float* __restrict__ bias, float* __restrict__ C)
{
    __shared__ __align__(16) float As[16][68];
    __shared__ __align__(16) float Bs[16][68];
    const int tid = threadIdx.x;
    const int bm = blockIdx.y * 64;
    const int bn = blockIdx.x * 64;
    const int tm = tid >> 4, tn = tid & 15;
    float acc[4][4] = {};
    for (int k0 = 0; k0 < 512; k0 += 16) {
        {   // A tile 64x16 -> transposed As[k][m]
            int row = tid >> 2, cg = (tid & 3) * 4;
            float4 v = *(const float4*)(A + (size_t)(bm + row) * 512 + k0 + cg);
            As[cg + 0][row] = v.x; As[cg + 1][row] = v.y;
            As[cg + 2][row] = v.z; As[cg + 3][row] = v.w;
        }
        {   // B tile 16x64
            int row = tid >> 4, col = (tid & 15) * 4;
            *(float4*)&Bs[row][col] = *(const float4*)(B + (size_t)(k0 + row) * 512 + bn + col);
        }
        __syncthreads();
#pragma unroll
        for (int k = 0; k < 16; k++) {
            float4 a = *(const float4*)&As[k][tm * 4];
            float4 b = *(const float4*)&Bs[k][tn * 4];
            float av[4] = {a.x, a.y, a.z, a.w};
            float bv[4] = {b.x, b.y, b.z, b.w};
#pragma unroll
            for (int i = 0; i < 4; i++)
#pragma unroll
                for (int jj = 0; jj < 4; jj++)
                    acc[i][jj] = fmaf(av[i], bv[jj], acc[i][jj]);
        }
        __syncthreads();
    }
    float4 bb = *(const float4*)(bias + bn + tn * 4);
#pragma unroll
    for (int i = 0; i < 4; i++) {
        float4 o;
        o.x = acc[i][0] + bb.x; o.y = acc[i][1] + bb.y;
        o.z = acc[i][2] + bb.z; o.w = acc[i][3] + bb.w;
        *(float4*)(C + (size_t)(bm + tm * 4 + i) * 512 + bn + tn * 4) = o;
    }
}

// ---------------- RNN recurrence: 8-CTA cluster, Whh slice in registers ----------------
// CTA rank owns outputs j in [rank*64, rank*64+64). Thread t: j = rank*64 + (t>>3),
// k-slice = (t&7)*64. h kept in SMEM (padded stride 68 => conflict-free LDS.128),
// double-buffered; new h broadcast to all 8 CTAs via st.shared::cluster; one
// cluster barrier per step.
__global__ void __cluster_dims__(8, 1, 1) __launch_bounds__(512, 1)
rnn_kernel(const float* __restrict__ Whh, const float* __restrict__ XW,
           float* __restrict__ Hout)
{
    __shared__ __align__(16) float sh_h[2][544];   // 8 slices * 68 words, x2 buffers
    const int tid  = threadIdx.x;
    const int s    = tid & 7;
    const int jloc = tid >> 3;
    const uint32_t rank = ctarank();
    const int j = (int)rank * 64 + jloc;

    float w[64];
#pragma unroll
    for (int i = 0; i < 64; i++) w[i] = Whh[(size_t)(s * 64 + i) * DD + j];

    for (int i = tid; i < 544; i += 512) sh_h[0][i] = 0.0f;   // h0 = 0
    __syncthreads();
    const uint32_t wbase = s2u(&sh_h[0][0]);

#pragma unroll 1
    for (int t = 0; t < NSEQ; t++) {
        const int p = t & 1;
        float xw = 0.0f;
        if (s == 0) xw = XW[(size_t)t * DD + j];
        const float* cb = &sh_h[p][s * 68];
        float a0 = 0, a1 = 0, a2 = 0, a3 = 0;
#pragma unroll
        for (int q = 0; q < 16; q++) {
            float4 h4 = *(const float4*)(cb + 4 * q);
            a0 = fmaf(h4.x, w[4 * q + 0], a0);
            a1 = fmaf(h4.y, w[4 * q + 1], a1);
            a2 = fmaf(h4.z, w[4 * q + 2], a2);
            a3 = fmaf(h4.w, w[4 * q + 3], a3);
        }
        float acc = (a0 + a1) + (a2 + a3);
        acc += __shfl_xor_sync(0xffffffffu, acc, 1);
        acc += __shfl_xor_sync(0xffffffffu, acc, 2);
        acc += __shfl_xor_sync(0xffffffffu, acc, 4);
        if (s == 0) {
            float h = tanhf(xw + acc);
            Hout[(size_t)t * DD + j] = h;
            uint32_t laddr = wbase + (uint32_t)(((1 - p) * 544 + (int)rank * 68 + jloc) * 4);
#pragma unroll
            for (int c = 0; c < 8; c++) dsmem_st(laddr, (uint32_t)c, h);
        }
        cluster_sync_();
    }
}

// ---------------- CRF backward logsumexp: 8-CTA cluster, T rows in registers ----------------
// c_new[u] = o[u] + m + ln2*log2( sum_v exp2( (T[u,v] + c[v] - m)*log2e ) ),
// m = max_v c[v] (computed as max of 8 per-CTA maxes, piggy-backed via DSMEM).
__global__ void __cluster_dims__(8, 1, 1) __launch_bounds__(512, 1)
crf_kernel(const float* __restrict__ T, const float* __restrict__ O,
           float* __restrict__ out)
{
    __shared__ __align__(16) float sh_c[2][544];
    __shared__ float sh_m[2][8];
    __shared__ float sh_wred[16];
    const int tid  = threadIdx.x;
    const int s    = tid & 7;
    const int uloc = tid >> 3;
    const uint32_t rank = ctarank();
    const int u = (int)rank * 64 + uloc;
    const float L2E  = 1.4426950408889634f;
    const float LN2f = 0.6931471805599453f;

    float tr[64];
#pragma unroll
    for (int i = 0; i < 64; i++) tr[i] = T[(size_t)u * VV + s * 64 + i] * L2E;

    for (int i = tid; i < 544; i += 512) sh_c[0][i] = -1e30f;
    __syncthreads();
    if (tid == 0) {
        float ce = O[(size_t)(NSEQ - 1) * VV + 1];   // c_init[EOS] = O[-1, EOS]
        sh_c[0][1] = ce;                              // padded index of v=1
#pragma unroll
        for (int r = 0; r < 8; r++) sh_m[0][r] = ce;
    }
    __syncthreads();
    const uint32_t cbase = s2u(&sh_c[0][0]);
    const uint32_t mbase = s2u(&sh_m[0][0]);

#pragma unroll 1
    for (int si = 0; si < NSEQ - 1; si++) {
        const int p = si & 1;
        const int row = (NSEQ - 2) - si;
        float o_u = 0.0f;
        if (s == 0) o_u = O[(size_t)row * VV + u];
        float m = sh_m[p][0];
#pragma unroll
        for (int r = 1; r < 8; r++) m = fmaxf(m, sh_m[p][r]);
        const float mm = m * L2E;
        const float* cb = &sh_c[p][s * 68];
        float a0 = 0, a1 = 0, a2 = 0, a3 = 0;
#pragma unroll
        for (int q = 0; q < 16; q++) {
            float4 c4 = *(const float4*)(cb + 4 * q);
            a0 += ex2f_(fmaf(c4.x, L2E, tr[4 * q + 0]) - mm);
            a1 += ex2f_(fmaf(c4.y, L2E, tr[4 * q + 1]) - mm);
            a2 += ex2f_(fmaf(c4.z, L2E, tr[4 * q + 2]) - mm);
            a3 += ex2f_(fmaf(c4.w, L2E, tr[4 * q + 3]) - mm);
        }
        float acc = (a0 + a1) + (a2 + a3);
        acc += __shfl_xor_sync(0xffffffffu, acc, 1);
        acc += __shfl_xor_sync(0xffffffffu, acc, 2);
        acc += __shfl_xor_sync(0xffffffffu, acc, 4);

        float cn = 0.0f, wmax = -1e30f;
        if (s == 0) {
            cn = o_u + m + lg2f_(acc) * LN2f;
            wmax = cn;
        }
        wmax = fmaxf(wmax, __shfl_xor_sync(0xffffffffu, wmax, 8));
        wmax = fmaxf(wmax, __shfl_xor_sync(0xffffffffu, wmax, 16));
        if ((tid & 31) == 0) sh_wred[tid >> 5] = wmax;
        __syncthreads();
        if (tid == 0) {
            float cm = sh_wred[0];
#pragma unroll
            for (int wq = 1; wq < 16; wq++) cm = fmaxf(cm, sh_wred[wq]);
            uint32_t laddr = mbase + (uint32_t)(((1 - p) * 8 + (int)rank) * 4);
#pragma unroll
            for (int c = 0; c < 8; c++) dsmem_st(laddr, (uint32_t)c, cm);
        }
        if (s == 0) {
            uint32_t laddr = cbase + (uint32_t)(((1 - p) * 544 + (int)rank * 68 + uloc) * 4);
#pragma unroll
            for (int c = 0; c < 8; c++) dsmem_st(laddr, (uint32_t)c, cn);
            if (si == NSEQ - 2 && u == 0) out[0] = cn;   // final c[BOS]
        }
        cluster_sync_();
    }
}

// ---------------- launch ----------------
extern "C" void kernel_launch(void* const* d_in, const int* in_sizes, int n_in,
                              void* d_out, int out_size)
{
    const void*  nums = d_in[0];
    const float* emb  = (const float*)d_in[1];
    const float* Wxh1 = (const float*)d_in[2];
    const float* Whh1 = (const float*)d_in[3];
    const float* b1   = (const float*)d_in[4];
    const float* Wxh2 = (const float*)d_in[5];
    const float* Whh2 = (const float*)d_in[6];
    const float* b2   = (const float*)d_in[7];
    const float* Wl   = (const float*)d_in[8];
    const float* bl   = (const float*)d_in[9];
    const float* Tm   = (const float*)d_in[10];
    float* out = (float*)d_out;

    float *X, *XW, *H, *O;
    cudaGetSymbolAddress((void**)&X,  g_X);
    cudaGetSymbolAddress((void**)&XW, g_XW);
    cudaGetSymbolAddress((void**)&H,  g_H);
    cudaGetSymbolAddress((void**)&O,  g_O);

    detect_kernel<<<1, 256>>>((const int*)nums);
    gather_kernel<<<NSEQ, 128>>>(nums, emb);

    dim3 gg(512 / 64, NSEQ / 64);
    gemm_bias<<<gg, 256>>>(X, Wxh1, b1, XW);     // XW1 = X@Wxh1 + b1
    rnn_kernel<<<8, 512>>>(Whh1, XW, H);          // G
    gemm_bias<<<gg, 256>>>(H, Wxh2, b2, XW);      // XW2 = G@Wxh2 + b2
    rnn_kernel<<<8, 512>>>(Whh2, XW, H);          // H
    gemm_bias<<<gg, 256>>>(H, Wl, bl, O);         // O = H@Wl + bl
    crf_kernel<<<8, 512>>>(Tm, O, out);           // scalar c0[BOS]
}